// round 3
// baseline (speedup 1.0000x reference)
#include <cuda_runtime.h>

// ---------------- static scratch (no allocations allowed) ----------------
#define N1_CAP 200704            // 196 * 1024, >= n1 (100000)
#define N2_CAP 65536             // 64  * 1024, >= n2 (20000)
#define E0_CAP 2097152           // >= 1.6M edges
#define E1_CAP 524288            // >= 320K edges

__device__ float g_agg0[(size_t)N1_CAP * 128];
__device__ float g_h   [(size_t)N1_CAP * 128];
__device__ float g_agg1[(size_t)N2_CAP * 128];
__device__ int   g_deg0[N1_CAP], g_row0[N1_CAP], g_cur0[N1_CAP];
__device__ int   g_deg1[N2_CAP], g_row1[N2_CAP], g_cur1[N2_CAP];
__device__ int   g_part0[1024], g_part1[1024];
__device__ int   g_bin0[E0_CAP], g_bin1[E1_CAP];

// ---------------- histogram: deg[dst[e]] += 1 ----------------
__global__ void k_hist(const int* __restrict__ dst, int E, int* __restrict__ deg) {
    int e = blockIdx.x * blockDim.x + threadIdx.x;
    if (e < E) atomicAdd(&deg[dst[e]], 1);
}

// ---------------- 3-phase exclusive scan over a fixed cap ----------------
__global__ void k_scan_block(const int* __restrict__ in, int* __restrict__ out,
                             int* __restrict__ partials) {
    __shared__ int s[1024];
    int t = threadIdx.x;
    int gi = blockIdx.x * 1024 + t;
    int v = in[gi];
    s[t] = v;
    __syncthreads();
#pragma unroll
    for (int o = 1; o < 1024; o <<= 1) {
        int add = (t >= o) ? s[t - o] : 0;
        __syncthreads();
        s[t] += add;
        __syncthreads();
    }
    out[gi] = s[t] - v;                 // exclusive within block
    if (t == 1023) partials[blockIdx.x] = s[1023];
}

__global__ void k_scan_partials(int* __restrict__ partials, int n) {
    __shared__ int s[1024];
    int t = threadIdx.x;
    int v = (t < n) ? partials[t] : 0;
    s[t] = v;
    __syncthreads();
#pragma unroll
    for (int o = 1; o < 1024; o <<= 1) {
        int add = (t >= o) ? s[t - o] : 0;
        __syncthreads();
        s[t] += add;
        __syncthreads();
    }
    if (t < n) partials[t] = s[t] - v;  // exclusive
}

__global__ void k_scan_finalize(int* __restrict__ rowptr, int* __restrict__ cursor,
                                const int* __restrict__ partials) {
    int gi = blockIdx.x * 1024 + threadIdx.x;
    int v = rowptr[gi] + partials[blockIdx.x];
    rowptr[gi] = v;
    cursor[gi] = v;
}

// ---------------- scatter edges into CSR bins (store src ids) ----------------
__global__ void k_scatter(const int* __restrict__ src, const int* __restrict__ dst,
                          int E, int* __restrict__ cursor, int* __restrict__ bin) {
    int e = blockIdx.x * blockDim.x + threadIdx.x;
    if (e < E) {
        int p = atomicAdd(&cursor[dst[e]], 1);
        bin[p] = src[e];
    }
}

// ---------------- mean aggregation: one warp per destination node ----------------
__global__ __launch_bounds__(256) void k_agg(
    const float* __restrict__ feat, const int* __restrict__ rowptr,
    const int* __restrict__ deg, const int* __restrict__ bin,
    float* __restrict__ out, const int* __restrict__ np, int nfb, int ncap) {
    int w = (blockIdx.x * blockDim.x + threadIdx.x) >> 5;
    int lane = threadIdx.x & 31;
    int n = nfb;
    if (np) { int t = *np; if (t > 0 && t <= ncap) n = t; }
    if (w >= n) return;
    int start = rowptr[w];
    int d = deg[w];
    const float4* f = (const float4*)feat;
    float4 a0 = make_float4(0.f, 0.f, 0.f, 0.f);
    float4 a1 = make_float4(0.f, 0.f, 0.f, 0.f);
    int j = 0;
    for (; j + 2 <= d; j += 2) {
        int s0 = bin[start + j];
        int s1 = bin[start + j + 1];
        float4 v0 = f[(size_t)s0 * 32 + lane];
        float4 v1 = f[(size_t)s1 * 32 + lane];
        a0.x += v0.x; a0.y += v0.y; a0.z += v0.z; a0.w += v0.w;
        a1.x += v1.x; a1.y += v1.y; a1.z += v1.z; a1.w += v1.w;
    }
    if (j < d) {
        int s0 = bin[start + j];
        float4 v0 = f[(size_t)s0 * 32 + lane];
        a0.x += v0.x; a0.y += v0.y; a0.z += v0.z; a0.w += v0.w;
    }
    float inv = 1.0f / (float)(d > 1 ? d : 1);
    float4 r;
    r.x = (a0.x + a1.x) * inv;
    r.y = (a0.y + a1.y) * inv;
    r.z = (a0.z + a1.z) * inv;
    r.w = (a0.w + a1.w) * inv;
    ((float4*)out)[(size_t)w * 32 + lane] = r;
}

// ---------------- layer-0 fused GEMM: h = relu(agg@Wl + x@Wr + b) ----------------
// C[n1,128] = [A | X] (n1 x 256) @ [Wl ; Wr] (256 x 128), 128x128 tiles, 8x8 reg blocking.
__global__ __launch_bounds__(256, 2) void k_gemm0(
    const float* __restrict__ A, const float* __restrict__ X,
    const float* __restrict__ Wl, const float* __restrict__ Wr,
    const float* __restrict__ bias, float* __restrict__ H,
    const int* __restrict__ np, int nfb) {
    __shared__ float As[128][33];   // padded: column reads conflict-free
    __shared__ float Ws[32][128];
    int n = nfb;
    if (np) { int t = *np; if (t > 0 && t <= N1_CAP) n = t; }
    int row0 = blockIdx.x * 128;
    if (row0 >= n) return;
    int tid = threadIdx.x;
    int tr = tid >> 4;      // 0..15 -> 8 rows each
    int tc = tid & 15;      // 0..15 -> 8 cols each
    float acc[8][8];
#pragma unroll
    for (int i = 0; i < 8; i++)
#pragma unroll
        for (int j = 0; j < 8; j++) acc[i][j] = 0.f;

    for (int kc = 0; kc < 256; kc += 32) {
        const float* asrc = (kc < 128) ? A : X;
        const float* wsrc = (kc < 128) ? Wl : Wr;
        int kb = kc & 127;
        // load A tile (128 x 32)
#pragma unroll
        for (int i = 0; i < 4; i++) {
            int idx = tid + i * 256;       // 0..1023
            int r = idx >> 3;              // 0..127
            int c4 = idx & 7;              // 0..7 -> float4 column
            int gr = row0 + r;
            float4 v = make_float4(0.f, 0.f, 0.f, 0.f);
            if (gr < n) v = *(const float4*)&asrc[(size_t)gr * 128 + kb + c4 * 4];
            As[r][c4 * 4 + 0] = v.x;
            As[r][c4 * 4 + 1] = v.y;
            As[r][c4 * 4 + 2] = v.z;
            As[r][c4 * 4 + 3] = v.w;
        }
        // load W tile (32 x 128)
#pragma unroll
        for (int i = 0; i < 4; i++) {
            int idx = tid + i * 256;
            int kk = idx >> 5;             // 0..31
            int c4 = idx & 31;             // 0..31
            float4 v = *(const float4*)&wsrc[(size_t)(kb + kk) * 128 + c4 * 4];
            *(float4*)&Ws[kk][c4 * 4] = v;
        }
        __syncthreads();
#pragma unroll
        for (int kk = 0; kk < 32; kk++) {
            float a[8];
#pragma unroll
            for (int i = 0; i < 8; i++) a[i] = As[tr * 8 + i][kk];
            float4 w0 = *(const float4*)&Ws[kk][tc * 8];
            float4 w1 = *(const float4*)&Ws[kk][tc * 8 + 4];
            float w[8] = {w0.x, w0.y, w0.z, w0.w, w1.x, w1.y, w1.z, w1.w};
#pragma unroll
            for (int i = 0; i < 8; i++)
#pragma unroll
                for (int j = 0; j < 8; j++) acc[i][j] = fmaf(a[i], w[j], acc[i][j]);
        }
        __syncthreads();
    }
    float b[8];
#pragma unroll
    for (int j = 0; j < 8; j++) b[j] = bias[tc * 8 + j];
#pragma unroll
    for (int i = 0; i < 8; i++) {
        int r = row0 + tr * 8 + i;
        if (r < n) {
            float4 o0, o1;
            o0.x = fmaxf(acc[i][0] + b[0], 0.f);
            o0.y = fmaxf(acc[i][1] + b[1], 0.f);
            o0.z = fmaxf(acc[i][2] + b[2], 0.f);
            o0.w = fmaxf(acc[i][3] + b[3], 0.f);
            o1.x = fmaxf(acc[i][4] + b[4], 0.f);
            o1.y = fmaxf(acc[i][5] + b[5], 0.f);
            o1.z = fmaxf(acc[i][6] + b[6], 0.f);
            o1.w = fmaxf(acc[i][7] + b[7], 0.f);
            *(float4*)&H[(size_t)r * 128 + tc * 8] = o0;
            *(float4*)&H[(size_t)r * 128 + tc * 8 + 4] = o1;
        }
    }
}

// ---------------- layer-1 fused GEMM + bias + log_softmax ----------------
// One warp per output row, 4 rows per warp. W' (256 x 47) in smem.
__global__ __launch_bounds__(256) void k_gemm1(
    const float* __restrict__ AGG, const float* __restrict__ Hd,
    const float* __restrict__ Wl, const float* __restrict__ Wr,
    const float* __restrict__ bias, float* __restrict__ out, int n2) {
    __shared__ float Ws[256 * 47];   // 47.0 KB
    for (int idx = threadIdx.x; idx < 128 * 47; idx += 256) {
        Ws[idx] = Wl[idx];
        Ws[128 * 47 + idx] = Wr[idx];
    }
    __syncthreads();
    int wid = threadIdx.x >> 5;
    int lane = threadIdx.x & 31;
    int c1 = (lane < 15) ? (lane + 32) : 46;   // clamped second column
    bool v1 = (lane < 15);

    for (int it = 0; it < 4; it++) {
        int r = blockIdx.x * 32 + wid * 4 + it;
        if (r >= n2) continue;
        float areg[8];
#pragma unroll
        for (int j = 0; j < 4; j++) areg[j] = AGG[(size_t)r * 128 + lane + 32 * j];
#pragma unroll
        for (int j = 0; j < 4; j++) areg[4 + j] = Hd[(size_t)r * 128 + lane + 32 * j];
        float acc0 = bias[lane];
        float acc1 = v1 ? bias[lane + 32] : 0.f;
#pragma unroll
        for (int seg = 0; seg < 8; seg++) {
            float as = areg[seg];
#pragma unroll
            for (int kk = 0; kk < 32; kk++) {
                float av = __shfl_sync(0xffffffffu, as, kk);
                int k = seg * 32 + kk;
                acc0 = fmaf(av, Ws[k * 47 + lane], acc0);
                acc1 = fmaf(av, Ws[k * 47 + c1], acc1);
            }
        }
        // log_softmax over 47 values: lanes 0..31 hold cols 0..31, lanes 0..14 hold 32..46
        float m = fmaxf(acc0, v1 ? acc1 : -1e30f);
#pragma unroll
        for (int o = 16; o > 0; o >>= 1) m = fmaxf(m, __shfl_xor_sync(0xffffffffu, m, o));
        float s = expf(acc0 - m) + (v1 ? expf(acc1 - m) : 0.f);
#pragma unroll
        for (int o = 16; o > 0; o >>= 1) s += __shfl_xor_sync(0xffffffffu, s, o);
        float ls = logf(s);
        out[(size_t)r * 47 + lane] = acc0 - m - ls;
        if (v1) out[(size_t)r * 47 + lane + 32] = acc1 - m - ls;
    }
}

// ---------------- launch ----------------
extern "C" void kernel_launch(void* const* d_in, const int* in_sizes, int n_in,
                              void* d_out, int out_size) {
    const float* x    = (const float*)d_in[0];
    const int*   src0 = (const int*)d_in[1];
    const int*   dst0 = (const int*)d_in[2];
    const int*   src1 = (const int*)d_in[3];
    const int*   dst1 = (const int*)d_in[4];
    const int E0 = in_sizes[1];
    const int E1 = in_sizes[3];
    const int n2 = out_size / 47;

    // scalars n1,n2 are inputs 5,6 when present; weights are the last 6 inputs
    const int wb = n_in - 6;
    const int* n1p = (n_in >= 13) ? (const int*)d_in[5] : nullptr;
    const float* Wl0 = (const float*)d_in[wb + 0];
    const float* bl0 = (const float*)d_in[wb + 1];
    const float* Wr0 = (const float*)d_in[wb + 2];
    const float* Wl1 = (const float*)d_in[wb + 3];
    const float* bl1 = (const float*)d_in[wb + 4];
    const float* Wr1 = (const float*)d_in[wb + 5];
    float* out = (float*)d_out;

    void *p;
    int *deg0, *row0, *cur0, *bin0, *part0;
    int *deg1, *row1, *cur1, *bin1, *part1;
    float *agg0, *h, *agg1;
    cudaGetSymbolAddress(&p, g_deg0); deg0 = (int*)p;
    cudaGetSymbolAddress(&p, g_row0); row0 = (int*)p;
    cudaGetSymbolAddress(&p, g_cur0); cur0 = (int*)p;
    cudaGetSymbolAddress(&p, g_bin0); bin0 = (int*)p;
    cudaGetSymbolAddress(&p, g_part0); part0 = (int*)p;
    cudaGetSymbolAddress(&p, g_deg1); deg1 = (int*)p;
    cudaGetSymbolAddress(&p, g_row1); row1 = (int*)p;
    cudaGetSymbolAddress(&p, g_cur1); cur1 = (int*)p;
    cudaGetSymbolAddress(&p, g_bin1); bin1 = (int*)p;
    cudaGetSymbolAddress(&p, g_part1); part1 = (int*)p;
    cudaGetSymbolAddress(&p, g_agg0); agg0 = (float*)p;
    cudaGetSymbolAddress(&p, g_h);    h    = (float*)p;
    cudaGetSymbolAddress(&p, g_agg1); agg1 = (float*)p;

    cudaMemsetAsync(deg0, 0, N1_CAP * sizeof(int), 0);
    cudaMemsetAsync(deg1, 0, N2_CAP * sizeof(int), 0);

    // ---- layer 0: CSR build ----
    k_hist<<<(E0 + 255) / 256, 256>>>(dst0, E0, deg0);
    k_scan_block<<<N1_CAP / 1024, 1024>>>(deg0, row0, part0);
    k_scan_partials<<<1, 1024>>>(part0, N1_CAP / 1024);
    k_scan_finalize<<<N1_CAP / 1024, 1024>>>(row0, cur0, part0);
    k_scatter<<<(E0 + 255) / 256, 256>>>(src0, dst0, E0, cur0, bin0);

    // ---- layer 0: mean aggregate + GEMM(relu) ----
    k_agg<<<(N1_CAP * 32 + 255) / 256, 256>>>(x, row0, deg0, bin0, agg0, n1p, 100000, N1_CAP);
    k_gemm0<<<N1_CAP / 128, 256>>>(agg0, x, Wl0, Wr0, bl0, h, n1p, 100000);

    // ---- layer 1: CSR build ----
    k_hist<<<(E1 + 255) / 256, 256>>>(dst1, E1, deg1);
    k_scan_block<<<N2_CAP / 1024, 1024>>>(deg1, row1, part1);
    k_scan_partials<<<1, 1024>>>(part1, N2_CAP / 1024);
    k_scan_finalize<<<N2_CAP / 1024, 1024>>>(row1, cur1, part1);
    k_scatter<<<(E1 + 255) / 256, 256>>>(src1, dst1, E1, cur1, bin1);

    // ---- layer 1: mean aggregate + GEMM + log_softmax ----
    k_agg<<<((size_t)n2 * 32 + 255) / 256, 256>>>(h, row1, deg1, bin1, agg1, nullptr, n2, N2_CAP);
    k_gemm1<<<(n2 + 31) / 32, 256>>>(agg1, h, Wl1, Wr1, bl1, out, n2);
}

// round 4
// speedup vs baseline: 1.0492x; 1.0492x over previous
#include <cuda_runtime.h>

// ---------------- static scratch (no allocations allowed) ----------------
#define N1_CAP 200704            // 196 * 1024, >= n1 (100000)
#define N2_CAP 65536             // 64  * 1024, >= n2 (20000)
#define E0_CAP 2097152           // >= 1.6M edges
#define E1_CAP 524288            // >= 320K edges
#define NB1 (N1_CAP / 1024)      // 196
#define NB2 (N2_CAP / 1024)      // 64

__device__ float g_agg0[(size_t)N1_CAP * 128];
__device__ float g_h   [(size_t)N1_CAP * 128];
__device__ float g_agg1[(size_t)N2_CAP * 128];
__device__ int   g_deg0[N1_CAP], g_row0[N1_CAP], g_cur0[N1_CAP];
__device__ int   g_deg1[N2_CAP], g_row1[N2_CAP], g_cur1[N2_CAP];
__device__ int   g_part0[1024], g_part1[1024];
__device__ int   g_bin0[E0_CAP], g_bin1[E1_CAP];

// ---------------- packed f32x2 helpers ----------------
typedef unsigned long long u64;
__device__ __forceinline__ u64 pack2(float lo, float hi) {
    u64 r; asm("mov.b64 %0, {%1, %2};" : "=l"(r) : "f"(lo), "f"(hi)); return r;
}
__device__ __forceinline__ void fma2(u64& d, u64 a, u64 b) {
    asm("fma.rn.f32x2 %0, %1, %2, %0;" : "+l"(d) : "l"(a), "l"(b));
}
__device__ __forceinline__ float2 unpack2(u64 v) {
    float lo, hi; asm("mov.b64 {%0, %1}, %2;" : "=f"(lo), "=f"(hi) : "l"(v));
    return make_float2(lo, hi);
}

// ---------------- zero both degree arrays ----------------
__global__ void k_zero2(int* __restrict__ d0, int* __restrict__ d1) {
    int i = blockIdx.x * blockDim.x + threadIdx.x;
    if (i < N1_CAP) d0[i] = 0;
    if (i < N2_CAP) d1[i] = 0;
}

// ---------------- merged histogram (both layers) ----------------
__global__ void k_hist2(const int* __restrict__ dst0, int E0, int* __restrict__ deg0,
                        const int* __restrict__ dst1, int E1, int* __restrict__ deg1) {
    int e = blockIdx.x * blockDim.x + threadIdx.x;
    if (e < E0) atomicAdd(&deg0[dst0[e]], 1);
    else if (e < E0 + E1) atomicAdd(&deg1[dst1[e - E0]], 1);
}

// ---------------- merged 3-phase exclusive scan ----------------
__global__ void k_scan_block2(const int* __restrict__ in0, int* __restrict__ out0,
                              int* __restrict__ p0,
                              const int* __restrict__ in1, int* __restrict__ out1,
                              int* __restrict__ p1) {
    __shared__ int s[1024];
    int t = threadIdx.x;
    int b = blockIdx.x;
    const int* in; int* out; int* partials; int lb;
    if (b < NB1) { in = in0; out = out0; partials = p0; lb = b; }
    else         { in = in1; out = out1; partials = p1; lb = b - NB1; }
    int gi = lb * 1024 + t;
    int v = in[gi];
    s[t] = v;
    __syncthreads();
#pragma unroll
    for (int o = 1; o < 1024; o <<= 1) {
        int add = (t >= o) ? s[t - o] : 0;
        __syncthreads();
        s[t] += add;
        __syncthreads();
    }
    out[gi] = s[t] - v;
    if (t == 1023) partials[lb] = s[1023];
}

__global__ void k_scan_partials2(int* __restrict__ p0, int* __restrict__ p1) {
    __shared__ int s[1024];
    int t = threadIdx.x;
    int* partials = (blockIdx.x == 0) ? p0 : p1;
    int n = (blockIdx.x == 0) ? NB1 : NB2;
    int v = (t < n) ? partials[t] : 0;
    s[t] = v;
    __syncthreads();
#pragma unroll
    for (int o = 1; o < 1024; o <<= 1) {
        int add = (t >= o) ? s[t - o] : 0;
        __syncthreads();
        s[t] += add;
        __syncthreads();
    }
    if (t < n) partials[t] = s[t] - v;
}

__global__ void k_scan_finalize2(int* __restrict__ r0, int* __restrict__ c0,
                                 const int* __restrict__ p0,
                                 int* __restrict__ r1, int* __restrict__ c1,
                                 const int* __restrict__ p1) {
    int b = blockIdx.x;
    int* rowptr; int* cursor; const int* partials; int lb;
    if (b < NB1) { rowptr = r0; cursor = c0; partials = p0; lb = b; }
    else         { rowptr = r1; cursor = c1; partials = p1; lb = b - NB1; }
    int gi = lb * 1024 + threadIdx.x;
    int v = rowptr[gi] + partials[lb];
    rowptr[gi] = v;
    cursor[gi] = v;
}

// ---------------- merged scatter ----------------
__global__ void k_scatter2(const int* __restrict__ src0, const int* __restrict__ dst0, int E0,
                           int* __restrict__ cur0, int* __restrict__ bin0,
                           const int* __restrict__ src1, const int* __restrict__ dst1, int E1,
                           int* __restrict__ cur1, int* __restrict__ bin1) {
    int e = blockIdx.x * blockDim.x + threadIdx.x;
    if (e < E0) {
        int p = atomicAdd(&cur0[dst0[e]], 1);
        bin0[p] = src0[e];
    } else if (e < E0 + E1) {
        int ee = e - E0;
        int p = atomicAdd(&cur1[dst1[ee]], 1);
        bin1[p] = src1[ee];
    }
}

// ---------------- mean aggregation: one warp per destination node ----------------
__global__ __launch_bounds__(256) void k_agg(
    const float* __restrict__ feat, const int* __restrict__ rowptr,
    const int* __restrict__ deg, const int* __restrict__ bin,
    float* __restrict__ out, const int* __restrict__ np, int nfb, int ncap) {
    int w = (blockIdx.x * blockDim.x + threadIdx.x) >> 5;
    int lane = threadIdx.x & 31;
    int n = nfb;
    if (np) { int t = *np; if (t > 0 && t <= ncap) n = t; }
    if (w >= n) return;
    int start = rowptr[w];
    int d = deg[w];
    const float4* f = (const float4*)feat;
    float4 a0 = make_float4(0.f, 0.f, 0.f, 0.f);
    float4 a1 = make_float4(0.f, 0.f, 0.f, 0.f);
    int j = 0;
    for (; j + 2 <= d; j += 2) {
        int s0 = bin[start + j];
        int s1 = bin[start + j + 1];
        float4 v0 = f[(size_t)s0 * 32 + lane];
        float4 v1 = f[(size_t)s1 * 32 + lane];
        a0.x += v0.x; a0.y += v0.y; a0.z += v0.z; a0.w += v0.w;
        a1.x += v1.x; a1.y += v1.y; a1.z += v1.z; a1.w += v1.w;
    }
    if (j < d) {
        int s0 = bin[start + j];
        float4 v0 = f[(size_t)s0 * 32 + lane];
        a0.x += v0.x; a0.y += v0.y; a0.z += v0.z; a0.w += v0.w;
    }
    float inv = 1.0f / (float)(d > 1 ? d : 1);
    float4 r;
    r.x = (a0.x + a1.x) * inv;
    r.y = (a0.y + a1.y) * inv;
    r.z = (a0.z + a1.z) * inv;
    r.w = (a0.w + a1.w) * inv;
    ((float4*)out)[(size_t)w * 32 + lane] = r;
}

// ---------------- layer-0 fused GEMM: h = relu(agg@Wl + x@Wr + b) ----------------
// C[n1,128] = [A | X] (n1 x 256) @ [Wl ; Wr] (256 x 128), 128x128 tiles,
// 8x8 register blocking executed as 8x4 packed fma.rn.f32x2.
__global__ __launch_bounds__(256, 2) void k_gemm0(
    const float* __restrict__ A, const float* __restrict__ X,
    const float* __restrict__ Wl, const float* __restrict__ Wr,
    const float* __restrict__ bias, float* __restrict__ H,
    const int* __restrict__ np, int nfb) {
    __shared__ float As[128][33];   // padded: column reads conflict-free
    __shared__ float Ws[32][128];
    int n = nfb;
    if (np) { int t = *np; if (t > 0 && t <= N1_CAP) n = t; }
    int row0 = blockIdx.x * 128;
    if (row0 >= n) return;
    int tid = threadIdx.x;
    int tr = tid >> 4;      // 0..15 -> 8 rows each
    int tc = tid & 15;      // 0..15 -> 8 cols each
    u64 acc2[8][4];
#pragma unroll
    for (int i = 0; i < 8; i++)
#pragma unroll
        for (int j = 0; j < 4; j++) acc2[i][j] = 0ull;

    for (int kc = 0; kc < 256; kc += 32) {
        const float* asrc = (kc < 128) ? A : X;
        const float* wsrc = (kc < 128) ? Wl : Wr;
        int kb = kc & 127;
        // load A tile (128 x 32)
#pragma unroll
        for (int i = 0; i < 4; i++) {
            int idx = tid + i * 256;       // 0..1023
            int r = idx >> 3;              // 0..127
            int c4 = idx & 7;              // 0..7 -> float4 column
            int gr = row0 + r;
            float4 v = make_float4(0.f, 0.f, 0.f, 0.f);
            if (gr < n) v = *(const float4*)&asrc[(size_t)gr * 128 + kb + c4 * 4];
            As[r][c4 * 4 + 0] = v.x;
            As[r][c4 * 4 + 1] = v.y;
            As[r][c4 * 4 + 2] = v.z;
            As[r][c4 * 4 + 3] = v.w;
        }
        // load W tile (32 x 128)
#pragma unroll
        for (int i = 0; i < 4; i++) {
            int idx = tid + i * 256;
            int kk = idx >> 5;             // 0..31
            int c4 = idx & 31;             // 0..31
            float4 v = *(const float4*)&wsrc[(size_t)(kb + kk) * 128 + c4 * 4];
            *(float4*)&Ws[kk][c4 * 4] = v;
        }
        __syncthreads();
#pragma unroll
        for (int kk = 0; kk < 32; kk++) {
            u64 aa[8];
#pragma unroll
            for (int i = 0; i < 8; i++) {
                float a = As[tr * 8 + i][kk];
                aa[i] = pack2(a, a);
            }
            float4 w0 = *(const float4*)&Ws[kk][tc * 8];
            float4 w1 = *(const float4*)&Ws[kk][tc * 8 + 4];
            u64 ww[4];
            ww[0] = pack2(w0.x, w0.y);
            ww[1] = pack2(w0.z, w0.w);
            ww[2] = pack2(w1.x, w1.y);
            ww[3] = pack2(w1.z, w1.w);
#pragma unroll
            for (int i = 0; i < 8; i++)
#pragma unroll
                for (int j = 0; j < 4; j++) fma2(acc2[i][j], aa[i], ww[j]);
        }
        __syncthreads();
    }
    float b[8];
#pragma unroll
    for (int j = 0; j < 8; j++) b[j] = bias[tc * 8 + j];
#pragma unroll
    for (int i = 0; i < 8; i++) {
        int r = row0 + tr * 8 + i;
        if (r < n) {
            float2 p0 = unpack2(acc2[i][0]);
            float2 p1 = unpack2(acc2[i][1]);
            float2 p2 = unpack2(acc2[i][2]);
            float2 p3 = unpack2(acc2[i][3]);
            float4 o0, o1;
            o0.x = fmaxf(p0.x + b[0], 0.f);
            o0.y = fmaxf(p0.y + b[1], 0.f);
            o0.z = fmaxf(p1.x + b[2], 0.f);
            o0.w = fmaxf(p1.y + b[3], 0.f);
            o1.x = fmaxf(p2.x + b[4], 0.f);
            o1.y = fmaxf(p2.y + b[5], 0.f);
            o1.z = fmaxf(p3.x + b[6], 0.f);
            o1.w = fmaxf(p3.y + b[7], 0.f);
            *(float4*)&H[(size_t)r * 128 + tc * 8] = o0;
            *(float4*)&H[(size_t)r * 128 + tc * 8 + 4] = o1;
        }
    }
}

// ---------------- layer-1 fused GEMM + bias + log_softmax ----------------
// One warp per output row, 4 rows per warp. W' (256 x 47) in smem.
__global__ __launch_bounds__(256) void k_gemm1(
    const float* __restrict__ AGG, const float* __restrict__ Hd,
    const float* __restrict__ Wl, const float* __restrict__ Wr,
    const float* __restrict__ bias, float* __restrict__ out, int n2) {
    __shared__ float Ws[256 * 47];   // 47.0 KB
    for (int idx = threadIdx.x; idx < 128 * 47; idx += 256) {
        Ws[idx] = Wl[idx];
        Ws[128 * 47 + idx] = Wr[idx];
    }
    __syncthreads();
    int wid = threadIdx.x >> 5;
    int lane = threadIdx.x & 31;
    int c1 = (lane < 15) ? (lane + 32) : 46;   // clamped second column
    bool v1 = (lane < 15);

    for (int it = 0; it < 4; it++) {
        int r = blockIdx.x * 32 + wid * 4 + it;
        if (r >= n2) continue;
        float areg[8];
#pragma unroll
        for (int j = 0; j < 4; j++) areg[j] = AGG[(size_t)r * 128 + lane + 32 * j];
#pragma unroll
        for (int j = 0; j < 4; j++) areg[4 + j] = Hd[(size_t)r * 128 + lane + 32 * j];
        float acc0 = bias[lane];
        float acc1 = v1 ? bias[lane + 32] : 0.f;
#pragma unroll
        for (int seg = 0; seg < 8; seg++) {
            float as = areg[seg];
#pragma unroll
            for (int kk = 0; kk < 32; kk++) {
                float av = __shfl_sync(0xffffffffu, as, kk);
                int k = seg * 32 + kk;
                acc0 = fmaf(av, Ws[k * 47 + lane], acc0);
                acc1 = fmaf(av, Ws[k * 47 + c1], acc1);
            }
        }
        // log_softmax over 47 values: lanes 0..31 hold cols 0..31, lanes 0..14 hold 32..46
        float m = fmaxf(acc0, v1 ? acc1 : -1e30f);
#pragma unroll
        for (int o = 16; o > 0; o >>= 1) m = fmaxf(m, __shfl_xor_sync(0xffffffffu, m, o));
        float s = expf(acc0 - m) + (v1 ? expf(acc1 - m) : 0.f);
#pragma unroll
        for (int o = 16; o > 0; o >>= 1) s += __shfl_xor_sync(0xffffffffu, s, o);
        float ls = logf(s);
        out[(size_t)r * 47 + lane] = acc0 - m - ls;
        if (v1) out[(size_t)r * 47 + lane + 32] = acc1 - m - ls;
    }
}

// ---------------- launch ----------------
extern "C" void kernel_launch(void* const* d_in, const int* in_sizes, int n_in,
                              void* d_out, int out_size) {
    const float* x    = (const float*)d_in[0];
    const int*   src0 = (const int*)d_in[1];
    const int*   dst0 = (const int*)d_in[2];
    const int*   src1 = (const int*)d_in[3];
    const int*   dst1 = (const int*)d_in[4];
    const int E0 = in_sizes[1];
    const int E1 = in_sizes[3];
    const int n2 = out_size / 47;

    // scalars n1,n2 are inputs 5,6 when present; weights are the last 6 inputs
    const int wb = n_in - 6;
    const int* n1p = (n_in >= 13) ? (const int*)d_in[5] : nullptr;
    const float* Wl0 = (const float*)d_in[wb + 0];
    const float* bl0 = (const float*)d_in[wb + 1];
    const float* Wr0 = (const float*)d_in[wb + 2];
    const float* Wl1 = (const float*)d_in[wb + 3];
    const float* bl1 = (const float*)d_in[wb + 4];
    const float* Wr1 = (const float*)d_in[wb + 5];
    float* out = (float*)d_out;

    void *p;
    int *deg0, *row0, *cur0, *bin0, *part0;
    int *deg1, *row1, *cur1, *bin1, *part1;
    float *agg0, *h, *agg1;
    cudaGetSymbolAddress(&p, g_deg0); deg0 = (int*)p;
    cudaGetSymbolAddress(&p, g_row0); row0 = (int*)p;
    cudaGetSymbolAddress(&p, g_cur0); cur0 = (int*)p;
    cudaGetSymbolAddress(&p, g_bin0); bin0 = (int*)p;
    cudaGetSymbolAddress(&p, g_part0); part0 = (int*)p;
    cudaGetSymbolAddress(&p, g_deg1); deg1 = (int*)p;
    cudaGetSymbolAddress(&p, g_row1); row1 = (int*)p;
    cudaGetSymbolAddress(&p, g_cur1); cur1 = (int*)p;
    cudaGetSymbolAddress(&p, g_bin1); bin1 = (int*)p;
    cudaGetSymbolAddress(&p, g_part1); part1 = (int*)p;
    cudaGetSymbolAddress(&p, g_agg0); agg0 = (float*)p;
    cudaGetSymbolAddress(&p, g_h);    h    = (float*)p;
    cudaGetSymbolAddress(&p, g_agg1); agg1 = (float*)p;

    // ---- CSR build for BOTH layers (merged launches) ----
    k_zero2<<<(N1_CAP + 255) / 256, 256>>>(deg0, deg1);
    k_hist2<<<(E0 + E1 + 255) / 256, 256>>>(dst0, E0, deg0, dst1, E1, deg1);
    k_scan_block2<<<NB1 + NB2, 1024>>>(deg0, row0, part0, deg1, row1, part1);
    k_scan_partials2<<<2, 1024>>>(part0, part1);
    k_scan_finalize2<<<NB1 + NB2, 1024>>>(row0, cur0, part0, row1, cur1, part1);
    k_scatter2<<<(E0 + E1 + 255) / 256, 256>>>(src0, dst0, E0, cur0, bin0,
                                               src1, dst1, E1, cur1, bin1);

    // ---- layer 0: mean aggregate + GEMM(relu) ----
    k_agg<<<(N1_CAP * 32 + 255) / 256, 256>>>(x, row0, deg0, bin0, agg0, n1p, 100000, N1_CAP);
    k_gemm0<<<N1_CAP / 128, 256>>>(agg0, x, Wl0, Wr0, bl0, h, n1p, 100000);

    // ---- layer 1: mean aggregate + GEMM + log_softmax ----
    k_agg<<<((size_t)n2 * 32 + 255) / 256, 256>>>(h, row1, deg1, bin1, agg1, nullptr, n2, N2_CAP);
    k_gemm1<<<(n2 + 31) / 32, 256>>>(agg1, h, Wl1, Wr1, bl1, out, n2);
}